// round 1
// baseline (speedup 1.0000x reference)
#include <cuda_runtime.h>
#include <math.h>
#include <stdint.h>
#include <stddef.h>

#define B_ 2048
#define I_ 512
#define H_ 512
#define L_ 32
#define D_ 1024
#define O_ 512

// ---------------- device scratch (no allocs allowed) ----------------
__device__ float g_Wcat_enc[4 * H_ * 2 * H_];   // [2048][1024] = [Wih|Whh]
__device__ float g_Wcat_dec[4 * H_ * 2 * H_];
__device__ float g_bias_enc[4 * H_];            // bih + bhh
__device__ float g_bias_dec[4 * H_];
__device__ float g_t2hT[D_ * H_];               // t2h_W transposed: [D][H]
__device__ float g_inp[B_ * H_];
__device__ float g_hx [B_ * H_];
__device__ float g_cx [B_ * H_];
__device__ float g_hx2[B_ * H_];
__device__ float g_cx2[B_ * H_];
__device__ float g_gates[B_ * 4 * H_];          // 16 MB
__device__ float g_zemb[L_ * B_ * H_];          // 128 MB: decoder inputs

// ---------------- generic NT GEMM: C = A @ W^T + bias ----------------
// A is [M,K] row-major. If A1 != nullptr, A is split: k<512 from A0 (ld 512),
// k>=512 from A1 (ld 512). W is [N,K] row-major. C has leading dim ldC.
#define BM 128
#define BN 128
#define BK 16

__device__ __forceinline__ float4 ld_split(const float* __restrict__ A0,
                                           const float* __restrict__ A1,
                                           int lda, int row, int k) {
    const float* base = A0;
    if (A1 != nullptr && k >= H_) { base = A1; k -= H_; }
    return *reinterpret_cast<const float4*>(base + (size_t)row * lda + k);
}

__global__ __launch_bounds__(256, 2)
void gemm_nt_kernel(const float* __restrict__ A0, const float* __restrict__ A1,
                    const float* __restrict__ W,  const float* __restrict__ bias,
                    float* __restrict__ C, int M, int N, int K, int ldC)
{
    __shared__ float As[2][BK][BM + 4];
    __shared__ float Ws[2][BK][BN + 4];

    const int t    = threadIdx.x;
    const int brow = blockIdx.y * BM;
    const int bcol = blockIdx.x * BN;
    const int lda  = (A1 != nullptr) ? H_ : K;

    // each thread loads 2 float4 of A and 2 of W per tile
    const int r0  = t >> 1;                  // row within tile (0..127)
    const int kq0 = (t & 1) * 2;             // float4 index pair: {0,1} or {2,3}
    const int kq1 = kq0 + 1;

    float4 pa0, pa1, pw0, pw1;

    // prologue: tile 0
    pa0 = ld_split(A0, A1, lda, brow + r0, 0 + kq0 * 4);
    pa1 = ld_split(A0, A1, lda, brow + r0, 0 + kq1 * 4);
    pw0 = *reinterpret_cast<const float4*>(W + (size_t)(bcol + r0) * K + kq0 * 4);
    pw1 = *reinterpret_cast<const float4*>(W + (size_t)(bcol + r0) * K + kq1 * 4);
    {
        As[0][kq0*4+0][r0]=pa0.x; As[0][kq0*4+1][r0]=pa0.y; As[0][kq0*4+2][r0]=pa0.z; As[0][kq0*4+3][r0]=pa0.w;
        As[0][kq1*4+0][r0]=pa1.x; As[0][kq1*4+1][r0]=pa1.y; As[0][kq1*4+2][r0]=pa1.z; As[0][kq1*4+3][r0]=pa1.w;
        Ws[0][kq0*4+0][r0]=pw0.x; Ws[0][kq0*4+1][r0]=pw0.y; Ws[0][kq0*4+2][r0]=pw0.z; Ws[0][kq0*4+3][r0]=pw0.w;
        Ws[0][kq1*4+0][r0]=pw1.x; Ws[0][kq1*4+1][r0]=pw1.y; Ws[0][kq1*4+2][r0]=pw1.z; Ws[0][kq1*4+3][r0]=pw1.w;
    }
    __syncthreads();

    float acc[8][8];
    #pragma unroll
    for (int i = 0; i < 8; i++)
        #pragma unroll
        for (int j = 0; j < 8; j++) acc[i][j] = 0.f;

    const int tx = t & 15, ty = t >> 4;
    const int mo = ty * 8, no = tx * 8;
    const int nk = K / BK;

    for (int kt = 0; kt < nk; kt++) {
        const int cur = kt & 1;
        if (kt + 1 < nk) {
            const int k0 = (kt + 1) * BK;
            pa0 = ld_split(A0, A1, lda, brow + r0, k0 + kq0 * 4);
            pa1 = ld_split(A0, A1, lda, brow + r0, k0 + kq1 * 4);
            pw0 = *reinterpret_cast<const float4*>(W + (size_t)(bcol + r0) * K + k0 + kq0 * 4);
            pw1 = *reinterpret_cast<const float4*>(W + (size_t)(bcol + r0) * K + k0 + kq1 * 4);
        }
        #pragma unroll
        for (int kk = 0; kk < BK; kk++) {
            float a[8], b[8];
            #pragma unroll
            for (int i = 0; i < 8; i++) a[i] = As[cur][kk][mo + i];
            #pragma unroll
            for (int j = 0; j < 8; j++) b[j] = Ws[cur][kk][no + j];
            #pragma unroll
            for (int i = 0; i < 8; i++)
                #pragma unroll
                for (int j = 0; j < 8; j++)
                    acc[i][j] = fmaf(a[i], b[j], acc[i][j]);
        }
        if (kt + 1 < nk) {
            const int nb = cur ^ 1;
            As[nb][kq0*4+0][r0]=pa0.x; As[nb][kq0*4+1][r0]=pa0.y; As[nb][kq0*4+2][r0]=pa0.z; As[nb][kq0*4+3][r0]=pa0.w;
            As[nb][kq1*4+0][r0]=pa1.x; As[nb][kq1*4+1][r0]=pa1.y; As[nb][kq1*4+2][r0]=pa1.z; As[nb][kq1*4+3][r0]=pa1.w;
            Ws[nb][kq0*4+0][r0]=pw0.x; Ws[nb][kq0*4+1][r0]=pw0.y; Ws[nb][kq0*4+2][r0]=pw0.z; Ws[nb][kq0*4+3][r0]=pw0.w;
            Ws[nb][kq1*4+0][r0]=pw1.x; Ws[nb][kq1*4+1][r0]=pw1.y; Ws[nb][kq1*4+2][r0]=pw1.z; Ws[nb][kq1*4+3][r0]=pw1.w;
        }
        __syncthreads();
    }

    #pragma unroll
    for (int i = 0; i < 8; i++) {
        const size_t off = (size_t)(brow + mo + i) * ldC + bcol + no;
        #pragma unroll
        for (int j = 0; j < 8; j++)
            C[off + j] = acc[i][j] + bias[bcol + no + j];
    }
}

// ---------------- pointwise LSTM cell ----------------
__device__ __forceinline__ float sigmoidf_(float x) { return 1.f / (1.f + expf(-x)); }

__global__ void lstm_pointwise(const float* __restrict__ gates,
                               float* __restrict__ hx, float* __restrict__ cx)
{
    const int idx = blockIdx.x * blockDim.x + threadIdx.x;
    if (idx >= B_ * H_) return;
    const int b = idx >> 9, h = idx & (H_ - 1);
    const float* g = gates + (size_t)b * (4 * H_);
    const float ii = sigmoidf_(g[h]);
    const float ff = sigmoidf_(g[h + H_]);
    const float gg = tanhf    (g[h + 2 * H_]);
    const float oo = sigmoidf_(g[h + 3 * H_]);
    const float c  = ff * cx[idx] + ii * gg;
    cx[idx] = c;
    hx[idx] = oo * tanhf(c);
}

// ---------------- softmax + straight-through + gathered inp ----------------
__global__ __launch_bounds__(256)
void softmax_st_kernel(const float* __restrict__ logits_base,  // d_out logits region [B][L][D]
                       const float* __restrict__ gumbel,       // [L][B][D]
                       int t,
                       float* __restrict__ onehot_base,        // d_out one_hot region [B][L][D]
                       float* __restrict__ messages,           // d_out messages [B][L]
                       const float* __restrict__ t2hT,         // [D][H]
                       const float* __restrict__ t2h_b,
                       float* __restrict__ inp,                // [B][H]
                       float* __restrict__ zembt)              // [B][H] slot t
{
    const int b   = blockIdx.x;
    const int tid = threadIdx.x;
    const float* pre = logits_base + (size_t)b * (L_ * D_) + (size_t)t * D_;
    const float* gm  = gumbel + ((size_t)t * B_ + b) * D_;

    float y[4];
    float vmax = -INFINITY; int imax = 0;
    #pragma unroll
    for (int q = 0; q < 4; q++) {
        const int d = tid + q * 256;
        y[q] = pre[d] + gm[d];
        if (y[q] > vmax) { vmax = y[q]; imax = d; }
    }
    __shared__ float sv[256];
    __shared__ int   si[256];
    sv[tid] = vmax; si[tid] = imax;
    __syncthreads();
    for (int s = 128; s > 0; s >>= 1) {
        if (tid < s) {
            const float ov = sv[tid + s]; const int oi = si[tid + s];
            if (ov > sv[tid] || (ov == sv[tid] && oi < si[tid])) { sv[tid] = ov; si[tid] = oi; }
        }
        __syncthreads();
    }
    vmax = sv[0]; imax = si[0];

    float lsum = 0.f;
    #pragma unroll
    for (int q = 0; q < 4; q++) lsum += expf(y[q] - vmax);
    __shared__ float ss[256];
    ss[tid] = lsum;
    __syncthreads();
    for (int s = 128; s > 0; s >>= 1) {
        if (tid < s) ss[tid] += ss[tid + s];
        __syncthreads();
    }
    const float s_amax = 1.f / ss[0];            // soft[amax]
    const float zval   = s_amax + (1.f - s_amax); // straight-through value

    float* oh = onehot_base + (size_t)b * (L_ * D_) + (size_t)t * D_;
    #pragma unroll
    for (int q = 0; q < 4; q++) {
        const int d = tid + q * 256;
        oh[d] = (d == imax) ? zval : 0.f;
    }
    if (tid == 0) messages[(size_t)b * L_ + t] = (float)imax;

    // inp = z @ t2h_W^T + b  ==  zval * t2h_W[:, imax] + t2h_b  (all other z exactly 0)
    const float* wrow = t2hT + (size_t)imax * H_;
    #pragma unroll
    for (int q = 0; q < 2; q++) {
        const int h = tid + q * 256;
        const float p = zval * wrow[h];
        const float v = p + t2h_b[h];
        inp  [(size_t)b * H_ + h] = v;
        zembt[(size_t)b * H_ + h] = v;
    }
}

// ---------------- packing / transpose / zero ----------------
__global__ void pack_lstm_kernel(const float* __restrict__ Wih, const float* __restrict__ Whh,
                                 const float* __restrict__ bih, const float* __restrict__ bhh,
                                 float* __restrict__ Wcat, float* __restrict__ bias)
{
    const int idx = blockIdx.x * 256 + threadIdx.x;
    if (idx < 4 * H_ * 2 * H_) {
        const int r = idx >> 10, k = idx & 1023;
        Wcat[idx] = (k < H_) ? Wih[(size_t)r * H_ + k] : Whh[(size_t)r * H_ + (k - H_)];
    }
    if (idx < 4 * H_) bias[idx] = bih[idx] + bhh[idx];
}

__global__ void transpose_t2h_kernel(const float* __restrict__ W, float* __restrict__ WT)
{
    const int idx = blockIdx.x * 256 + threadIdx.x;   // over D*H
    if (idx >= D_ * H_) return;
    const int d = idx / H_, h = idx - d * H_;
    WT[idx] = W[(size_t)h * D_ + d];
}

__global__ void zero_kernel(float* __restrict__ p, int n)
{
    const int idx = blockIdx.x * 256 + threadIdx.x;
    if (idx < n) p[idx] = 0.f;
}

// ---------------- host ----------------
extern "C" void kernel_launch(void* const* d_in, const int* in_sizes, int n_in,
                              void* d_out, int out_size)
{
    const float* x       = (const float*)d_in[0];
    const float* gumbel  = (const float*)d_in[1];
    const float* in_W    = (const float*)d_in[2];
    const float* in_b    = (const float*)d_in[3];
    const float* out_W   = (const float*)d_in[4];
    const float* out_b   = (const float*)d_in[5];
    const float* enc_Wih = (const float*)d_in[6];
    const float* enc_Whh = (const float*)d_in[7];
    const float* enc_bih = (const float*)d_in[8];
    const float* enc_bhh = (const float*)d_in[9];
    const float* dec_Wih = (const float*)d_in[10];
    const float* dec_Whh = (const float*)d_in[11];
    const float* dec_bih = (const float*)d_in[12];
    const float* dec_bhh = (const float*)d_in[13];
    const float* h2t_W   = (const float*)d_in[14];
    const float* h2t_b   = (const float*)d_in[15];
    const float* t2h_W   = (const float*)d_in[16];
    const float* t2h_b   = (const float*)d_in[17];

    float* out        = (float*)d_out;
    float* out_recon  = out;
    float* out_onehot = out + (size_t)B_ * O_;
    float* out_logits = out_onehot + (size_t)B_ * L_ * D_;
    float* out_msg    = out_logits + (size_t)B_ * L_ * D_;

    float *Wce, *Wcd, *be, *bd, *t2hT, *inp, *hx, *cx, *hx2, *cx2, *gates, *zemb;
    cudaGetSymbolAddress((void**)&Wce,   g_Wcat_enc);
    cudaGetSymbolAddress((void**)&Wcd,   g_Wcat_dec);
    cudaGetSymbolAddress((void**)&be,    g_bias_enc);
    cudaGetSymbolAddress((void**)&bd,    g_bias_dec);
    cudaGetSymbolAddress((void**)&t2hT,  g_t2hT);
    cudaGetSymbolAddress((void**)&inp,   g_inp);
    cudaGetSymbolAddress((void**)&hx,    g_hx);
    cudaGetSymbolAddress((void**)&cx,    g_cx);
    cudaGetSymbolAddress((void**)&hx2,   g_hx2);
    cudaGetSymbolAddress((void**)&cx2,   g_cx2);
    cudaGetSymbolAddress((void**)&gates, g_gates);
    cudaGetSymbolAddress((void**)&zemb,  g_zemb);

    // weight prep
    pack_lstm_kernel<<<(4 * H_ * 2 * H_ + 255) / 256, 256>>>(enc_Wih, enc_Whh, enc_bih, enc_bhh, Wce, be);
    pack_lstm_kernel<<<(4 * H_ * 2 * H_ + 255) / 256, 256>>>(dec_Wih, dec_Whh, dec_bih, dec_bhh, Wcd, bd);
    transpose_t2h_kernel<<<(D_ * H_ + 255) / 256, 256>>>(t2h_W, t2hT);

    // init states: hx=0, inp=0, cx = x @ in_W^T + in_b  ;  decoder hx2=cx2=0
    zero_kernel<<<(B_ * H_ + 255) / 256, 256>>>(inp, B_ * H_);
    zero_kernel<<<(B_ * H_ + 255) / 256, 256>>>(hx,  B_ * H_);
    zero_kernel<<<(B_ * H_ + 255) / 256, 256>>>(hx2, B_ * H_);
    zero_kernel<<<(B_ * H_ + 255) / 256, 256>>>(cx2, B_ * H_);
    gemm_nt_kernel<<<dim3(H_ / BN, B_ / BM), 256>>>(x, nullptr, in_W, in_b, cx, B_, H_, I_, H_);

    // ---- encoder ----
    for (int t = 0; t < L_; t++) {
        gemm_nt_kernel<<<dim3((4 * H_) / BN, B_ / BM), 256>>>(inp, hx, Wce, be, gates, B_, 4 * H_, 2 * H_, 4 * H_);
        lstm_pointwise<<<(B_ * H_) / 256, 256>>>(gates, hx, cx);
        gemm_nt_kernel<<<dim3(D_ / BN, B_ / BM), 256>>>(hx, nullptr, h2t_W, h2t_b,
                                                        out_logits + (size_t)t * D_, B_, D_, H_, L_ * D_);
        softmax_st_kernel<<<B_, 256>>>(out_logits, gumbel, t, out_onehot, out_msg,
                                       t2hT, t2h_b, inp, zemb + (size_t)t * B_ * H_);
    }

    // ---- decoder ----
    for (int t = 0; t < L_; t++) {
        gemm_nt_kernel<<<dim3((4 * H_) / BN, B_ / BM), 256>>>(zemb + (size_t)t * B_ * H_, hx2, Wcd, bd,
                                                              gates, B_, 4 * H_, 2 * H_, 4 * H_);
        lstm_pointwise<<<(B_ * H_) / 256, 256>>>(gates, hx2, cx2);
    }
    gemm_nt_kernel<<<dim3(O_ / BN, B_ / BM), 256>>>(hx2, nullptr, out_W, out_b, out_recon, B_, O_, H_, O_);
}